// round 5
// baseline (speedup 1.0000x reference)
#include <cuda_runtime.h>
#include <math.h>
#include <math_constants.h>

// Problem constants
#define HEAD_DIM 128
#define NQH      32
#define NKVH     8
#define HIDDEN   4096
#define SEQ      2048
#define KV_COLS  1024          // NKVH * HEAD_DIM
#define NCHUNK   64
#define CHUNK_ROWS 64          // 4096 / NCHUNK
#define TOT_COLS 6144          // HIDDEN + 2*KV_COLS
#define TOT4     (TOT_COLS/4)

// ---------------- scratch (no allocations allowed) ----------------
__device__ float  d_partial[NCHUNK * TOT_COLS];  // colsum partials (1.5 MB)
__device__ float  d_cq[HIDDEN];                  // colsum(Wq)
__device__ float  d_ck[KV_COLS];                 // colsum(Wk)
__device__ float  d_cv[KV_COLS];                 // colsum(Wv)
__device__ float2 d_trig[64 * SEQ];              // (cos,sin)(delta*omega_i), head-independent
__device__ float  d_g[NQH * SEQ];                // per-head relative-position score table
__device__ float  d_M[NQH * HIDDEN];             // M[h,j] = sum_d cv[kvh,d]*Wo[h*128+d, j]
__device__ float  d_w[NQH * SEQ];                // w[h,q] = sum_k attn(h,q,k)*ids[k]
__device__ unsigned short d_sortidx[NQH * SEQ];  // per-head deltas sorted by g descending

// ============ K1: colsums of Wq/Wk/Wv (z=0..2) + trig table (z=3), fused ============
__global__ void __launch_bounds__(256) stage1_trig(const float* __restrict__ Wq,
                                                   const float* __restrict__ Wk,
                                                   const float* __restrict__ Wv) {
    if (blockIdx.z == 3) {
        int base = (blockIdx.y * 4 + blockIdx.x) * 256 + threadIdx.x;
        const double LN10000 = 9.210340371976184;   // ln(10000)
#pragma unroll
        for (int rep = 0; rep < 2; rep++) {
            int idx = base + rep * 65536;
            int i = idx >> 11;                       // frequency index 0..63
            int delta = idx & (SEQ - 1);             // 0..2047
            double omega = exp(-((double)(2 * i) / 128.0) * LN10000);
            double sn, cs;
            sincos((double)delta * omega, &sn, &cs);
            d_trig[idx] = make_float2((float)cs, (float)sn);
        }
        return;
    }
    int mat = blockIdx.z;
    const float* W;
    int C4, off4;
    if (mat == 0)      { W = Wq; C4 = HIDDEN / 4;  off4 = 0; }
    else if (mat == 1) { W = Wk; C4 = KV_COLS / 4; off4 = HIDDEN / 4; }
    else               { W = Wv; C4 = KV_COLS / 4; off4 = (HIDDEN + KV_COLS) / 4; }

    int col4 = blockIdx.x * 256 + threadIdx.x;
    if (col4 >= C4) return;
    const float4* p = (const float4*)W + (size_t)blockIdx.y * CHUNK_ROWS * C4 + col4;
    float4 s = make_float4(0.f, 0.f, 0.f, 0.f);
#pragma unroll 8
    for (int r = 0; r < CHUNK_ROWS; r++) {
        float4 v = p[(size_t)r * C4];
        s.x += v.x; s.y += v.y; s.z += v.z; s.w += v.w;
    }
    ((float4*)d_partial)[blockIdx.y * TOT4 + off4 + col4] = s;
}

// ============ K2: reduce partials (deterministic, float4) ============
__global__ void __launch_bounds__(256) colsum_stage2() {
    int col4 = blockIdx.x * 256 + threadIdx.x;   // 0..1535
    float4 s = make_float4(0.f, 0.f, 0.f, 0.f);
#pragma unroll
    for (int c = 0; c < NCHUNK; c++) {
        float4 v = ((const float4*)d_partial)[c * TOT4 + col4];
        s.x += v.x; s.y += v.y; s.z += v.z; s.w += v.w;
    }
    if (col4 < HIDDEN / 4)                       ((float4*)d_cq)[col4] = s;
    else if (col4 < (HIDDEN + KV_COLS) / 4)      ((float4*)d_ck)[col4 - HIDDEN / 4] = s;
    else                                         ((float4*)d_cv)[col4 - (HIDDEN + KV_COLS) / 4] = s;
}

// ============ K3: compute_M (x<4) + compute_g (x>=4), fused ============
__global__ void __launch_bounds__(256) m_and_g(const float* __restrict__ Wo) {
    int h = blockIdx.y;
    int kvh = h >> 2;
    if (blockIdx.x < 4) {
        __shared__ float scv[HEAD_DIM];
        if (threadIdx.x < HEAD_DIM) scv[threadIdx.x] = d_cv[kvh * HEAD_DIM + threadIdx.x];
        __syncthreads();
        int j4 = blockIdx.x * 256 + threadIdx.x;     // 0..1023
        const float4* wp = (const float4*)Wo + (size_t)(h * HEAD_DIM) * (HIDDEN / 4) + j4;
        float4 s = make_float4(0.f, 0.f, 0.f, 0.f);
#pragma unroll 8
        for (int d = 0; d < HEAD_DIM; d++) {
            float c = scv[d];
            float4 v = wp[(size_t)d * (HIDDEN / 4)];
            s.x += c * v.x; s.y += c * v.y; s.z += c * v.z; s.w += c * v.w;
        }
        ((float4*)d_M)[h * (HIDDEN / 4) + j4] = s;
    } else {
        __shared__ float sA[64], sB[64];
        if (threadIdx.x < 64) {
            int i = threadIdx.x;
            float q1 = d_cq[h * HEAD_DIM + i];
            float q2 = d_cq[h * HEAD_DIM + 64 + i];
            float k1 = d_ck[kvh * HEAD_DIM + i];
            float k2 = d_ck[kvh * HEAD_DIM + 64 + i];
            sA[i] = q1 * k1 + q2 * k2;
            sB[i] = q1 * k2 - q2 * k1;
        }
        __syncthreads();
        int delta = (blockIdx.x - 4) * 256 + threadIdx.x;   // 0..2047
        float acc = 0.f;
#pragma unroll 8
        for (int i = 0; i < 64; i++) {
            float2 t = d_trig[i * SEQ + delta];             // coalesced, L2-resident
            acc += sA[i] * t.x + sB[i] * t.y;
        }
        d_g[h * SEQ + delta] = acc;
    }
}

// ============ K4: per-head bitonic sort of deltas by g descending ============
__global__ void __launch_bounds__(1024) sort_g() {
    __shared__ unsigned long long s_arr[SEQ];
    int h = blockIdx.x;
    int tid = threadIdx.x;
    for (int i = tid; i < SEQ; i += 1024) {
        unsigned u = __float_as_uint(d_g[h * SEQ + i]);
        // monotone map: ascending in m <=> ascending float; key = ~m => descending float
        unsigned m = (u & 0x80000000u) ? ~u : (u | 0x80000000u);
        s_arr[i] = ((unsigned long long)(~m) << 32) | (unsigned)i;
    }
    for (unsigned k = 2; k <= SEQ; k <<= 1) {
        for (unsigned j = k >> 1; j > 0; j >>= 1) {
            __syncthreads();
            for (unsigned i = tid; i < SEQ; i += 1024) {
                unsigned ixj = i ^ j;
                if (ixj > i) {
                    bool up = ((i & k) == 0);
                    unsigned long long a = s_arr[i], b = s_arr[ixj];
                    if ((a > b) == up) { s_arr[i] = b; s_arr[ixj] = a; }
                }
            }
        }
    }
    __syncthreads();
    for (int p = tid; p < SEQ; p += 1024)
        d_sortidx[h * SEQ + p] = (unsigned short)(s_arr[p] & 0xFFFFu);
}

// ============ K5: attention via sorted-delta prefix pruning ============
// u(q,k) = ids[k]*g[q-k], score = alpha*u, alpha = ids[q]/sqrt(128) >= 0, ids <= 99.
// Since u <= 99*g[delta], the contributing set {u > m - 60/alpha} lies in a prefix of
// the g-descending-sorted deltas. Adaptive scan with running max; stop when
// 99*g_next <= m_run - 60/alpha. Fallback to exact dense scan when m <= 60/alpha
// (covers ids==0 contributors, all-negative-g rows, and alpha==0 -> uniform softmax).
__global__ void __launch_bounds__(256) attention(const int* __restrict__ ids) {
    __shared__ float s_g[SEQ];
    __shared__ float s_ids[SEQ];
    __shared__ unsigned short s_srt[SEQ];
    int h = blockIdx.y;
    int tid = threadIdx.x;
    for (int i = tid; i < SEQ; i += 256) {
        s_g[i] = d_g[h * SEQ + i];
        s_ids[i] = (float)ids[i];
        s_srt[i] = d_sortidx[h * SEQ + i];
    }
    __syncthreads();

    int warp = tid >> 5, lane = tid & 31;
    int slot = blockIdx.x * 8 + warp;               // 0..127
    const float INV_SQRT_D = 0.08838834764831845f;  // 1/sqrt(128)
    const unsigned FULL = 0xffffffffu;

    for (int r = 0; r < 16; r++) {
        int q = slot + 128 * r;
        float alpha = s_ids[q] * INV_SQRT_D;
        float wwin = 60.f / alpha;                  // +INF when alpha==0
        float wout = 0.f;
        bool dense = (q < 128);

        if (!dense) {
            // ---- adaptive scan over g-sorted deltas ----
            float ml = -CUDART_INF_F;
            float mw = -CUDART_INF_F;
            int T = 64;
            for (int t = 0; t < 64; t++) {
                int sp = t * 32 + lane;
                int dlt = s_srt[sp];
                float u = (dlt <= q) ? s_ids[q - dlt] * s_g[dlt] : -CUDART_INF_F;
                ml = fmaxf(ml, u);
                mw = ml;
#pragma unroll
                for (int off = 16; off; off >>= 1)
                    mw = fmaxf(mw, __shfl_xor_sync(FULL, mw, off));
                if (t == 63) { T = 64; break; }
                float gnext = s_g[s_srt[(t + 1) * 32]];   // broadcast LDS
                if (99.f * gnext <= mw - wwin) { T = t + 1; break; }
            }
            float m = mw;
            if (m <= wwin) {
                dense = true;                       // rare: tiny max / alpha==0
            } else {
                float thr = m - wwin;
                float l = 0.f, a = 0.f;
                for (int t = 0; t < T; t++) {
                    int sp = t * 32 + lane;
                    int dlt = s_srt[sp];
                    if (dlt <= q) {
                        float idk = s_ids[q - dlt];
                        float u = idk * s_g[dlt];
                        if (u > thr) {
                            float e = __expf(alpha * (u - m));
                            l += e; a += e * idk;
                        }
                    }
                }
#pragma unroll
                for (int off = 16; off; off >>= 1) {
                    l += __shfl_xor_sync(FULL, l, off);
                    a += __shfl_xor_sync(FULL, a, off);
                }
                wout = a / l;
            }
        }

        if (dense) {
            // ---- exact dense two-pass over k in [0, q] ----
            const float* gq = s_g + q;
            float ml = -CUDART_INF_F;
            for (int k = lane; k <= q; k += 32)
                ml = fmaxf(ml, s_ids[k] * gq[-k]);
#pragma unroll
            for (int off = 16; off; off >>= 1)
                ml = fmaxf(ml, __shfl_xor_sync(FULL, ml, off));
            float m = ml;
            float thr = m - wwin;                   // -INF if alpha==0 -> keep all
            float l = 0.f, a = 0.f;
            for (int k = lane; k <= q; k += 32) {
                float idk = s_ids[k];
                float u = idk * gq[-k];
                if (u > thr) {
                    float e = __expf(alpha * (u - m));
                    l += e; a += e * idk;
                }
            }
#pragma unroll
            for (int off = 16; off; off >>= 1) {
                l += __shfl_xor_sync(FULL, l, off);
                a += __shfl_xor_sync(FULL, a, off);
            }
            wout = a / l;
        }
        if (lane == 0) d_w[h * SEQ + q] = wout;
    }
}

// ============ K6: final y[q, j] = sum_h w[h,q] * M[h,j] ============
__global__ void __launch_bounds__(256) final_proj(float* __restrict__ out) {
    __shared__ float s_w[32 * 32];
    int jb = blockIdx.x, qb = blockIdx.y;           // 16 x 64 grid
    int tid = threadIdx.x;
    for (int i = tid; i < 32 * 32; i += 256) {
        int h = i >> 5, qq = i & 31;
        s_w[i] = d_w[h * SEQ + qb * 32 + qq];
    }
    __syncthreads();
    int j = jb * 256 + tid;
    float Mreg[32];
#pragma unroll
    for (int h = 0; h < 32; h++) Mreg[h] = d_M[h * HIDDEN + j];
    for (int qq = 0; qq < 32; qq++) {
        float acc = 0.f;
#pragma unroll
        for (int h = 0; h < 32; h++) acc += s_w[h * 32 + qq] * Mreg[h];
        out[(size_t)(qb * 32 + qq) * HIDDEN + j] = acc;
    }
}

// ---------------- launch ----------------
extern "C" void kernel_launch(void* const* d_in, const int* in_sizes, int n_in,
                              void* d_out, int out_size) {
    // Map inputs by element count: 2048: input_ids (first), position_ids;
    // 16777216: Wq, Wo ; 4194304: Wk, Wv
    const int* ids = nullptr;
    const float *Wq = nullptr, *Wk = nullptr, *Wv = nullptr, *Wo = nullptr;
    int seen2048 = 0, seen16m = 0, seen4m = 0;
    for (int i = 0; i < n_in; i++) {
        int sz = in_sizes[i];
        if (sz == SEQ) {
            if (seen2048++ == 0) ids = (const int*)d_in[i];
        } else if (sz == HIDDEN * HIDDEN) {
            if (seen16m++ == 0) Wq = (const float*)d_in[i];
            else                Wo = (const float*)d_in[i];
        } else if (sz == HIDDEN * KV_COLS) {
            if (seen4m++ == 0)  Wk = (const float*)d_in[i];
            else                Wv = (const float*)d_in[i];
        }
    }
    float* out = (float*)d_out;

    stage1_trig<<<dim3(4, NCHUNK, 4), 256>>>(Wq, Wk, Wv);
    colsum_stage2<<<TOT4 / 256, 256>>>();
    m_and_g<<<dim3(12, NQH), 256>>>(Wo);
    sort_g<<<NQH, 1024>>>();
    attention<<<dim3(SEQ / 128, NQH), 256>>>(ids);
    final_proj<<<dim3(HIDDEN / 256, SEQ / 32), 256>>>(out);
}

// round 6
// speedup vs baseline: 1.2332x; 1.2332x over previous
#include <cuda_runtime.h>
#include <math.h>
#include <math_constants.h>

// Problem constants
#define HEAD_DIM 128
#define NQH      32
#define NKVH     8
#define HIDDEN   4096
#define SEQ      2048
#define KV_COLS  1024          // NKVH * HEAD_DIM
#define NCHUNK   32
#define CHUNK_ROWS 128         // 4096 / NCHUNK
#define TOT_COLS 6144          // HIDDEN + 2*KV_COLS

// ---------------- scratch (no allocations allowed) ----------------
__device__ float  d_partial[NCHUNK * TOT_COLS];  // colsum partials
__device__ float  d_cq[HIDDEN];                  // colsum(Wq)
__device__ float  d_ck[KV_COLS];                 // colsum(Wk)
__device__ float  d_cv[KV_COLS];                 // colsum(Wv)
__device__ float2 d_trig[64 * SEQ];              // (cos,sin)(delta*omega_i), head-independent
__device__ float  d_g[NQH * SEQ];                // per-head relative-position score table
__device__ float  d_M[NQH * HIDDEN];             // M[h,j] = sum_d cv[kvh,d]*Wo[h*128+d, j]
__device__ float  d_w[NQH * SEQ];                // w[h,q] = sum_k attn(h,q,k)*ids[k]

// ============ K1: scalar colsums of Wq/Wk/Wv (z=0..2, R2-proven) + trig (z=3) ============
__global__ void __launch_bounds__(256) stage1_trig(const float* __restrict__ Wq,
                                                   const float* __restrict__ Wk,
                                                   const float* __restrict__ Wv) {
    if (blockIdx.z == 3) {
        // trig: 64*2048 = 131072 entries; 512 blocks * 256 threads * 1 each
        int idx = (blockIdx.y * 16 + blockIdx.x) * 256 + threadIdx.x;
        int i = idx >> 11;                           // frequency index 0..63
        int delta = idx & (SEQ - 1);                 // 0..2047
        const double LN10000 = 9.210340371976184;   // ln(10000)
        double omega = exp(-((double)(2 * i) / 128.0) * LN10000);
        double sn, cs;
        sincos((double)delta * omega, &sn, &cs);
        d_trig[idx] = make_float2((float)cs, (float)sn);
        return;
    }
    int mat = blockIdx.z;
    const float* W;
    int C, off;
    if (mat == 0)      { W = Wq; C = HIDDEN;  off = 0; }
    else if (mat == 1) { W = Wk; C = KV_COLS; off = HIDDEN; }
    else               { W = Wv; C = KV_COLS; off = HIDDEN + KV_COLS; }

    int col = blockIdx.x * 256 + threadIdx.x;
    if (col >= C) return;
    const float* p = W + (size_t)blockIdx.y * CHUNK_ROWS * C + col;
    float s = 0.f;
#pragma unroll 8
    for (int r = 0; r < CHUNK_ROWS; r++) s += p[(size_t)r * C];
    d_partial[blockIdx.y * TOT_COLS + off + col] = s;
}

// ============ K2: reduce partials (deterministic, R2-proven) ============
__global__ void __launch_bounds__(256) colsum_stage2() {
    int col = blockIdx.x * 256 + threadIdx.x;   // 0..6143
    float s = 0.f;
#pragma unroll
    for (int c = 0; c < NCHUNK; c++) s += d_partial[c * TOT_COLS + col];
    if (col < HIDDEN)                 d_cq[col] = s;
    else if (col < HIDDEN + KV_COLS)  d_ck[col - HIDDEN] = s;
    else                              d_cv[col - HIDDEN - KV_COLS] = s;
}

// ============ K3: M[h,j] = sum_d cv[kvh*128+d] * Wo[(h*128+d)*HIDDEN + j] (R2-proven) ====
__global__ void __launch_bounds__(256) compute_M(const float* __restrict__ Wo) {
    int j = blockIdx.x * 256 + threadIdx.x;     // 0..4095
    int h = blockIdx.y;                         // 0..31
    int kvh = h >> 2;
    const float* wp = Wo + (size_t)(h * HEAD_DIM) * HIDDEN + j;
    const float* cv = d_cv + kvh * HEAD_DIM;
    float s = 0.f;
#pragma unroll 8
    for (int d = 0; d < HEAD_DIM; d++) s += cv[d] * wp[(size_t)d * HIDDEN];
    d_M[h * HIDDEN + j] = s;
}

// ============ K4: g table from trig (R2-proven) ============
__global__ void __launch_bounds__(256) compute_g() {
    __shared__ float sA[64], sB[64];
    int h = blockIdx.y;
    int kvh = h >> 2;
    if (threadIdx.x < 64) {
        int i = threadIdx.x;
        float q1 = d_cq[h * HEAD_DIM + i];
        float q2 = d_cq[h * HEAD_DIM + 64 + i];
        float k1 = d_ck[kvh * HEAD_DIM + i];
        float k2 = d_ck[kvh * HEAD_DIM + 64 + i];
        sA[i] = q1 * k1 + q2 * k2;
        sB[i] = q1 * k2 - q2 * k1;
    }
    __syncthreads();
    int delta = blockIdx.x * 256 + threadIdx.x;   // 0..2047
    float acc = 0.f;
#pragma unroll 8
    for (int i = 0; i < 64; i++) {
        float2 t = d_trig[i * SEQ + delta];       // coalesced, L2-resident (1 MB table)
        acc += sA[i] * t.x + sB[i] * t.y;
    }
    d_g[h * SEQ + delta] = acc;
}

// ============ K5: attention — float4 max pass + exact-chunk-pruned accumulate ============
// scores(q,k) = alpha * u,  u = ids[k]*g[q-k],  alpha = ids[q]/sqrt(128) >= 0.
// Pass 1 (vectorized): exact per-128-k-chunk maxima via float4 on both operands.
// The reversed g[q-k] access is float4-enabled by 4 shift-phased pre-reversed copies
// of g in smem; phase s=(q+1)&3 is warp-uniform. Pass 2 visits only chunks whose
// exact max exceeds m - 60/alpha (skipped terms < e^-60 -> below ref's fp32 floor).
__global__ void __launch_bounds__(256) attention(const int* __restrict__ ids) {
    __shared__ float  s_g[SEQ];                  // 8 KB
    __shared__ float  s_ids[SEQ];                // 8 KB
    __shared__ float4 s_gr4[4 * 512];            // 32 KB: s_gr4[s*512+j] =
                                                 //  (g[4j+s+3],g[4j+s+2],g[4j+s+1],g[4j+s])
    int h = blockIdx.y;
    int tid = threadIdx.x;
    for (int i = tid; i < SEQ; i += 256) {
        s_g[i] = d_g[h * SEQ + i];
        s_ids[i] = (float)ids[i];
    }
    __syncthreads();
    for (int t = tid; t < 2048; t += 256) {
        int s = t >> 9, j = t & 511;
        int b = 4 * j + s;
        float x = s_g[min(b + 3, SEQ - 1)];
        float y = s_g[min(b + 2, SEQ - 1)];
        float z = s_g[min(b + 1, SEQ - 1)];
        float w = s_g[b];
        s_gr4[s * 512 + j] = make_float4(x, y, z, w);
    }
    __syncthreads();

    int warp = tid >> 5, lane = tid & 31;
    int slot = blockIdx.x * 8 + warp;               // 0..127
    const float INV_SQRT_D = 0.08838834764831845f;  // 1/sqrt(128)
    const unsigned FULL = 0xffffffffu;
    const float4* idv = (const float4*)s_ids;

    for (int r = 0; r < 16; r++) {
        int q = slot + 128 * r;                     // strided: balances triangular work
        float alpha = s_ids[q] * INV_SQRT_D;
        const float* gq = s_g + q;                  // g[q-k] = gq[-k]
        float w;

        if (alpha == 0.f) {
            // all scores exactly 0 -> uniform softmax -> mean of ids[0..q]
            float ssum = 0.f;
            for (int k = lane; k <= q; k += 32) ssum += s_ids[k];
#pragma unroll
            for (int off = 16; off; off >>= 1) ssum += __shfl_xor_sync(FULL, ssum, off);
            w = ssum / (float)(q + 1);
        } else {
            int sphase = (q + 1) & 3;               // warp-uniform shift phase
            const float4* gr = s_gr4 + sphase * 512;

            // ---- pass 1: lane-local exact chunk maxima (16 chunks of 128 k) ----
            float cmax[16];
            float m = -CUDART_INF_F;
#pragma unroll
            for (int c = 0; c < 16; c++) {
                int kb = c << 7;
                float mc = -CUDART_INF_F;
                if (kb + 127 <= q) {
                    // full chunk, fully vectorized: lane owns k = kb+4*lane .. +3
                    int k0 = kb + 4 * lane;
                    float4 iv = idv[(c << 5) + lane];
                    float4 gv = gr[(q - k0 - 3) >> 2];   // (g[q-k0],g[q-k0-1],g[q-k0-2],g[q-k0-3])
                    mc = fmaxf(fmaxf(iv.x * gv.x, iv.y * gv.y),
                               fmaxf(iv.z * gv.z, iv.w * gv.w));
                } else if (kb <= q) {
                    // partial chunk: scalar with predication
#pragma unroll
                    for (int jj = 0; jj < 4; jj++) {
                        int k = kb + jj * 32 + lane;
                        float u = (k <= q) ? s_ids[k] * gq[-k] : -CUDART_INF_F;
                        mc = fmaxf(mc, u);
                    }
                }
                cmax[c] = mc;
                m = fmaxf(m, mc);
            }
#pragma unroll
            for (int off = 16; off; off >>= 1)
                m = fmaxf(m, __shfl_xor_sync(FULL, m, off));

            float thr = m - 60.f / alpha;           // u-domain threshold

            // ---- chunk selection: any lane's exact chunk max above thr ----
            unsigned sel = 0;
#pragma unroll
            for (int c = 0; c < 16; c++) {
                unsigned b = __ballot_sync(FULL, cmax[c] > thr);
                sel |= (b ? 1u : 0u) << c;
            }

            // ---- pass 2: accumulate over selected chunks only (typically 1) ----
            float l = 0.f, a = 0.f;
            while (sel) {
                int c = __ffs(sel) - 1; sel &= sel - 1;
                int kb = c << 7;
#pragma unroll
                for (int jj = 0; jj < 4; jj++) {
                    int k = kb + jj * 32 + lane;
                    if (k <= q) {
                        float idk = s_ids[k];
                        float u = idk * gq[-k];
                        if (u > thr) {
                            float e = __expf(alpha * (u - m));
                            l += e; a += e * idk;
                        }
                    }
                }
            }
#pragma unroll
            for (int off = 16; off; off >>= 1) {
                l += __shfl_xor_sync(FULL, l, off);
                a += __shfl_xor_sync(FULL, a, off);
            }
            w = a / l;
        }
        if (lane == 0) d_w[h * SEQ + q] = w;
    }
}

// ============ K6: final y[q, j] = sum_h w[h,q] * M[h,j] (R2-proven) ============
__global__ void __launch_bounds__(256) final_proj(float* __restrict__ out) {
    __shared__ float s_w[32 * 64];
    int jb = blockIdx.x, qb = blockIdx.y;
    int tid = threadIdx.x;
    for (int i = tid; i < 32 * 64; i += 256) {
        int h = i >> 6, qq = i & 63;
        s_w[i] = d_w[h * SEQ + qb * 64 + qq];
    }
    __syncthreads();
    int j = jb * 256 + tid;
    float Mreg[32];
#pragma unroll
    for (int h = 0; h < 32; h++) Mreg[h] = d_M[h * HIDDEN + j];
    for (int qq = 0; qq < 64; qq++) {
        float acc = 0.f;
#pragma unroll
        for (int h = 0; h < 32; h++) acc += s_w[h * 64 + qq] * Mreg[h];
        out[(size_t)(qb * 64 + qq) * HIDDEN + j] = acc;
    }
}

// ---------------- launch ----------------
extern "C" void kernel_launch(void* const* d_in, const int* in_sizes, int n_in,
                              void* d_out, int out_size) {
    // Map inputs by element count: 2048: input_ids (first), position_ids;
    // 16777216: Wq, Wo ; 4194304: Wk, Wv
    const int* ids = nullptr;
    const float *Wq = nullptr, *Wk = nullptr, *Wv = nullptr, *Wo = nullptr;
    int seen2048 = 0, seen16m = 0, seen4m = 0;
    for (int i = 0; i < n_in; i++) {
        int sz = in_sizes[i];
        if (sz == SEQ) {
            if (seen2048++ == 0) ids = (const int*)d_in[i];
        } else if (sz == HIDDEN * HIDDEN) {
            if (seen16m++ == 0) Wq = (const float*)d_in[i];
            else                Wo = (const float*)d_in[i];
        } else if (sz == HIDDEN * KV_COLS) {
            if (seen4m++ == 0)  Wk = (const float*)d_in[i];
            else                Wv = (const float*)d_in[i];
        }
    }
    float* out = (float*)d_out;

    stage1_trig<<<dim3(16, NCHUNK, 4), 256>>>(Wq, Wk, Wv);
    colsum_stage2<<<TOT_COLS / 256, 256>>>();
    compute_M<<<dim3(HIDDEN / 256, NQH), 256>>>(Wo);
    compute_g<<<dim3(SEQ / 256, NQH), 256>>>();
    attention<<<dim3(SEQ / 128, NQH), 256>>>(ids);
    final_proj<<<dim3(HIDDEN / 256, SEQ / 64), 256>>>(out);
}

// round 7
// speedup vs baseline: 1.2704x; 1.0301x over previous
#include <cuda_runtime.h>
#include <math.h>
#include <math_constants.h>

// Problem constants
#define HEAD_DIM 128
#define NQH      32
#define NKVH     8
#define HIDDEN   4096
#define SEQ      2048
#define KV_COLS  1024          // NKVH * HEAD_DIM
#define NCHUNK   128
#define CHUNK_ROWS 32          // 4096 / NCHUNK
#define TOT_COLS 6144          // HIDDEN + 2*KV_COLS
#define TOT4     (TOT_COLS/4)

// ---------------- scratch (no allocations allowed) ----------------
__device__ float  d_partial[NCHUNK * TOT_COLS];  // colsum partials (3 MB)
__device__ float  d_cq[HIDDEN];                  // colsum(Wq)
__device__ float  d_ck[KV_COLS];                 // colsum(Wk)
__device__ float  d_cv[KV_COLS];                 // colsum(Wv)
__device__ float2 d_trig[64 * SEQ];              // (cos,sin)(delta*omega_i), head-independent
__device__ float  d_g[NQH * SEQ];                // per-head relative-position score table
__device__ float  d_M[NQH * HIDDEN];             // M[h,j] = sum_d cv[kvh,d]*Wo[h*128+d, j]
__device__ float  d_w[NQH * SEQ];                // w[h,q] = sum_k attn(h,q,k)*ids[k]

// ============ K1: float4 colsums of Wq/Wk/Wv (z=0..2) + trig table (z=3) ============
__global__ void __launch_bounds__(256) stage1_trig(const float* __restrict__ Wq,
                                                   const float* __restrict__ Wk,
                                                   const float* __restrict__ Wv) {
    if (blockIdx.z == 3) {
        // trig: 64*2048 = 131072 entries; (4 x 128) blocks * 256 threads = exactly 1 each
        int idx = (blockIdx.y * 4 + blockIdx.x) * 256 + threadIdx.x;
        int i = idx >> 11;                           // frequency index 0..63
        int delta = idx & (SEQ - 1);                 // 0..2047
        const double LN10000 = 9.210340371976184;   // ln(10000)
        double omega = exp(-((double)(2 * i) / 128.0) * LN10000);
        double sn, cs;
        sincos((double)delta * omega, &sn, &cs);
        d_trig[idx] = make_float2((float)cs, (float)sn);
        return;
    }
    int mat = blockIdx.z;
    const float* W;
    int C4, off4;
    if (mat == 0)      { W = Wq; C4 = HIDDEN / 4;  off4 = 0; }
    else if (mat == 1) { W = Wk; C4 = KV_COLS / 4; off4 = HIDDEN / 4; }
    else               { W = Wv; C4 = KV_COLS / 4; off4 = (HIDDEN + KV_COLS) / 4; }

    int col4 = blockIdx.x * 256 + threadIdx.x;
    if (col4 >= C4) return;
    const float4* p = (const float4*)W + (size_t)blockIdx.y * CHUNK_ROWS * C4 + col4;
    float4 s = make_float4(0.f, 0.f, 0.f, 0.f);
#pragma unroll 8
    for (int r = 0; r < CHUNK_ROWS; r++) {
        float4 v = p[(size_t)r * C4];
        s.x += v.x; s.y += v.y; s.z += v.z; s.w += v.w;
    }
    ((float4*)d_partial)[blockIdx.y * TOT4 + off4 + col4] = s;
}

// ============ K2: reduce partials (deterministic) ============
__global__ void __launch_bounds__(256) colsum_stage2() {
    int col = blockIdx.x * 256 + threadIdx.x;   // 0..6143
    float s = 0.f;
#pragma unroll 16
    for (int c = 0; c < NCHUNK; c++) s += d_partial[c * TOT_COLS + col];
    if (col < HIDDEN)                 d_cq[col] = s;
    else if (col < HIDDEN + KV_COLS)  d_ck[col - HIDDEN] = s;
    else                              d_cv[col - HIDDEN - KV_COLS] = s;
}

// ============ K3: M[h,j] — float4, d-split across 4 warp-groups, 512 CTAs ============
__global__ void __launch_bounds__(256) compute_M(const float* __restrict__ Wo) {
    __shared__ float  scv[HEAD_DIM];
    __shared__ float4 s_part[4][64];
    int h = blockIdx.y;                          // 0..31
    int kvh = h >> 2;
    if (threadIdx.x < HEAD_DIM) scv[threadIdx.x] = d_cv[kvh * HEAD_DIM + threadIdx.x];
    __syncthreads();
    int sub = threadIdx.x >> 6;                  // 0..3 -> d range [sub*32, sub*32+32)
    int jl  = threadIdx.x & 63;                  // 0..63
    int j4  = blockIdx.x * 64 + jl;              // 0..1023
    const float4* wp = (const float4*)Wo
                     + (size_t)(h * HEAD_DIM + sub * 32) * (HIDDEN / 4) + j4;
    float4 s = make_float4(0.f, 0.f, 0.f, 0.f);
#pragma unroll 8
    for (int d = 0; d < 32; d++) {
        float c = scv[sub * 32 + d];
        float4 v = wp[(size_t)d * (HIDDEN / 4)];
        s.x += c * v.x; s.y += c * v.y; s.z += c * v.z; s.w += c * v.w;
    }
    s_part[sub][jl] = s;
    __syncthreads();
    if (threadIdx.x < 64) {
        float4 a = s_part[0][threadIdx.x], b = s_part[1][threadIdx.x];
        float4 c = s_part[2][threadIdx.x], d = s_part[3][threadIdx.x];
        float4 r = make_float4(a.x + b.x + c.x + d.x, a.y + b.y + c.y + d.y,
                               a.z + b.z + c.z + d.z, a.w + b.w + c.w + d.w);
        ((float4*)d_M)[h * (HIDDEN / 4) + blockIdx.x * 64 + threadIdx.x] = r;
    }
}

// ============ K4: g table — i-split across 4 warp-groups, 1024 CTAs ============
__global__ void __launch_bounds__(256) compute_g() {
    __shared__ float sA[64], sB[64];
    __shared__ float s_part[4][64];
    int h = blockIdx.y;
    int kvh = h >> 2;
    if (threadIdx.x < 64) {
        int i = threadIdx.x;
        float q1 = d_cq[h * HEAD_DIM + i];
        float q2 = d_cq[h * HEAD_DIM + 64 + i];
        float k1 = d_ck[kvh * HEAD_DIM + i];
        float k2 = d_ck[kvh * HEAD_DIM + 64 + i];
        sA[i] = q1 * k1 + q2 * k2;
        sB[i] = q1 * k2 - q2 * k1;
    }
    __syncthreads();
    int sub = threadIdx.x >> 6;                   // 0..3 -> i range [sub*16, sub*16+16)
    int jl  = threadIdx.x & 63;                   // 0..63
    int delta = blockIdx.x * 64 + jl;             // 0..2047
    float acc = 0.f;
#pragma unroll
    for (int t = 0; t < 16; t++) {
        int i = sub * 16 + t;
        float2 tr = d_trig[i * SEQ + delta];      // coalesced, L2-resident
        acc += sA[i] * tr.x + sB[i] * tr.y;
    }
    s_part[sub][jl] = acc;
    __syncthreads();
    if (threadIdx.x < 64) {
        float s = s_part[0][threadIdx.x] + s_part[1][threadIdx.x]
                + s_part[2][threadIdx.x] + s_part[3][threadIdx.x];
        d_g[h * SEQ + blockIdx.x * 64 + threadIdx.x] = s;
    }
}

// ============ K5: attention — float4 max pass + exact-chunk-pruned accumulate ============
// scores(q,k) = alpha * u,  u = ids[k]*g[q-k],  alpha = ids[q]/sqrt(128) >= 0.
// Pass 1 (vectorized): exact per-128-k-chunk maxima via float4 on both operands.
// The reversed g[q-k] access is float4-enabled by 4 shift-phased pre-reversed copies
// of g in smem; phase s=(q+1)&3 is warp-uniform. Pass 2 visits only chunks whose
// exact max exceeds m - 60/alpha (skipped terms < e^-60 -> below ref's fp32 floor).
__global__ void __launch_bounds__(256) attention(const int* __restrict__ ids) {
    __shared__ float  s_g[SEQ];                  // 8 KB
    __shared__ float  s_ids[SEQ];                // 8 KB
    __shared__ float4 s_gr4[4 * 512];            // 32 KB: s_gr4[s*512+j] =
                                                 //  (g[4j+s+3],g[4j+s+2],g[4j+s+1],g[4j+s])
    int h = blockIdx.y;
    int tid = threadIdx.x;
    for (int i = tid; i < SEQ; i += 256) {
        s_g[i] = d_g[h * SEQ + i];
        s_ids[i] = (float)ids[i];
    }
    __syncthreads();
    for (int t = tid; t < 2048; t += 256) {
        int s = t >> 9, j = t & 511;
        int b = 4 * j + s;
        float x = s_g[min(b + 3, SEQ - 1)];
        float y = s_g[min(b + 2, SEQ - 1)];
        float z = s_g[min(b + 1, SEQ - 1)];
        float w = s_g[b];
        s_gr4[s * 512 + j] = make_float4(x, y, z, w);
    }
    __syncthreads();

    int warp = tid >> 5, lane = tid & 31;
    int slot = blockIdx.x * 8 + warp;               // 0..127
    const float INV_SQRT_D = 0.08838834764831845f;  // 1/sqrt(128)
    const unsigned FULL = 0xffffffffu;
    const float4* idv = (const float4*)s_ids;

    for (int r = 0; r < 16; r++) {
        int q = slot + 128 * r;                     // strided: balances triangular work
        float alpha = s_ids[q] * INV_SQRT_D;
        const float* gq = s_g + q;                  // g[q-k] = gq[-k]
        float w;

        if (alpha == 0.f) {
            // all scores exactly 0 -> uniform softmax -> mean of ids[0..q]
            float ssum = 0.f;
            for (int k = lane; k <= q; k += 32) ssum += s_ids[k];
#pragma unroll
            for (int off = 16; off; off >>= 1) ssum += __shfl_xor_sync(FULL, ssum, off);
            w = ssum / (float)(q + 1);
        } else {
            int sphase = (q + 1) & 3;               // warp-uniform shift phase
            const float4* gr = s_gr4 + sphase * 512;

            // ---- pass 1: lane-local exact chunk maxima (16 chunks of 128 k) ----
            float cmax[16];
            float m = -CUDART_INF_F;
#pragma unroll
            for (int c = 0; c < 16; c++) {
                int kb = c << 7;
                float mc = -CUDART_INF_F;
                if (kb + 127 <= q) {
                    // full chunk, fully vectorized: lane owns k = kb+4*lane .. +3
                    int k0 = kb + 4 * lane;
                    float4 iv = idv[(c << 5) + lane];
                    float4 gv = gr[(q - k0 - 3) >> 2];   // (g[q-k0],g[q-k0-1],g[q-k0-2],g[q-k0-3])
                    mc = fmaxf(fmaxf(iv.x * gv.x, iv.y * gv.y),
                               fmaxf(iv.z * gv.z, iv.w * gv.w));
                } else if (kb <= q) {
                    // partial chunk: scalar with predication
#pragma unroll
                    for (int jj = 0; jj < 4; jj++) {
                        int k = kb + jj * 32 + lane;
                        float u = (k <= q) ? s_ids[k] * gq[-k] : -CUDART_INF_F;
                        mc = fmaxf(mc, u);
                    }
                }
                cmax[c] = mc;
                m = fmaxf(m, mc);
            }
#pragma unroll
            for (int off = 16; off; off >>= 1)
                m = fmaxf(m, __shfl_xor_sync(FULL, m, off));

            float thr = m - 60.f / alpha;           // u-domain threshold

            // ---- chunk selection: any lane's exact chunk max above thr ----
            unsigned sel = 0;
#pragma unroll
            for (int c = 0; c < 16; c++) {
                unsigned b = __ballot_sync(FULL, cmax[c] > thr);
                sel |= (b ? 1u : 0u) << c;
            }

            // ---- pass 2: accumulate over selected chunks only (typically 1) ----
            float l = 0.f, a = 0.f;
            while (sel) {
                int c = __ffs(sel) - 1; sel &= sel - 1;
                int kb = c << 7;
#pragma unroll
                for (int jj = 0; jj < 4; jj++) {
                    int k = kb + jj * 32 + lane;
                    if (k <= q) {
                        float idk = s_ids[k];
                        float u = idk * gq[-k];
                        if (u > thr) {
                            float e = __expf(alpha * (u - m));
                            l += e; a += e * idk;
                        }
                    }
                }
            }
#pragma unroll
            for (int off = 16; off; off >>= 1) {
                l += __shfl_xor_sync(FULL, l, off);
                a += __shfl_xor_sync(FULL, a, off);
            }
            w = a / l;
        }
        if (lane == 0) d_w[h * SEQ + q] = w;
    }
}

// ============ K6: final y[q, j] = sum_h w[h,q] * M[h,j] (proven) ============
__global__ void __launch_bounds__(256) final_proj(float* __restrict__ out) {
    __shared__ float s_w[32 * 64];
    int jb = blockIdx.x, qb = blockIdx.y;
    int tid = threadIdx.x;
    for (int i = tid; i < 32 * 64; i += 256) {
        int h = i >> 6, qq = i & 63;
        s_w[i] = d_w[h * SEQ + qb * 64 + qq];
    }
    __syncthreads();
    int j = jb * 256 + tid;
    float Mreg[32];
#pragma unroll
    for (int h = 0; h < 32; h++) Mreg[h] = d_M[h * HIDDEN + j];
    for (int qq = 0; qq < 64; qq++) {
        float acc = 0.f;
#pragma unroll
        for (int h = 0; h < 32; h++) acc += s_w[h * 64 + qq] * Mreg[h];
        out[(size_t)(qb * 64 + qq) * HIDDEN + j] = acc;
    }
}

// ---------------- launch ----------------
extern "C" void kernel_launch(void* const* d_in, const int* in_sizes, int n_in,
                              void* d_out, int out_size) {
    // Map inputs by element count: 2048: input_ids (first), position_ids;
    // 16777216: Wq, Wo ; 4194304: Wk, Wv
    const int* ids = nullptr;
    const float *Wq = nullptr, *Wk = nullptr, *Wv = nullptr, *Wo = nullptr;
    int seen2048 = 0, seen16m = 0, seen4m = 0;
    for (int i = 0; i < n_in; i++) {
        int sz = in_sizes[i];
        if (sz == SEQ) {
            if (seen2048++ == 0) ids = (const int*)d_in[i];
        } else if (sz == HIDDEN * HIDDEN) {
            if (seen16m++ == 0) Wq = (const float*)d_in[i];
            else                Wo = (const float*)d_in[i];
        } else if (sz == HIDDEN * KV_COLS) {
            if (seen4m++ == 0)  Wk = (const float*)d_in[i];
            else                Wv = (const float*)d_in[i];
        }
    }
    float* out = (float*)d_out;

    stage1_trig<<<dim3(4, NCHUNK, 4), 256>>>(Wq, Wk, Wv);
    colsum_stage2<<<TOT_COLS / 256, 256>>>();
    compute_M<<<dim3(16, NQH), 256>>>(Wo);
    compute_g<<<dim3(SEQ / 64, NQH), 256>>>();
    attention<<<dim3(SEQ / 128, NQH), 256>>>(ids);
    final_proj<<<dim3(HIDDEN / 256, SEQ / 64), 256>>>(out);
}